// round 17
// baseline (speedup 1.0000x reference)
#include <cuda_runtime.h>
#include <stdint.h>

#define HDIM 256
#define TS   256
#define BTOT 4096
#define BC   14                        // batch rows per CTA (7 pairs)
#define NBLK ((BTOT + BC - 1) / BC)    // 293 CTAs <= 296 concurrent at 2/SM

// W split into even/odd-g planes so each thread (q) gets coalesced 16B loads
// for both of its output features g0=2q, g1=2q+1:
//   g_WpA[h4*128 + q] = float4{ W[2q  ][4h4 .. 4h4+3] }
//   g_WpB[h4*128 + q] = float4{ W[2q+1][4h4 .. 4h4+3] }
__device__ float4 g_WpA[64 * 128];
__device__ float4 g_WpB[64 * 128];

__global__ void pack_w_kernel(const float* __restrict__ W) {
    int idx = blockIdx.x * blockDim.x + threadIdx.x;   // 0..16383
    int h4 = idx >> 8, g = idx & 255;
    float4 v = ((const float4*)W)[g * 64 + h4];
    int q = g >> 1;
    if (g & 1) g_WpB[(h4 << 7) + q] = v;
    else       g_WpA[(h4 << 7) + q] = v;
}

// Threefry-2x32, 20 rounds — matches jax._src.prng.threefry2x32 exactly.
__device__ __forceinline__ uint2 tf2x32(uint32_t k0, uint32_t k1, uint32_t c0, uint32_t c1) {
    uint32_t ks2 = k0 ^ k1 ^ 0x1BD11BDAu;
    uint32_t x0 = c0 + k0, x1 = c1 + k1;
#define TFR(r) { x0 += x1; x1 = __funnelshift_l(x1, x1, r); x1 ^= x0; }
    TFR(13) TFR(15) TFR(26) TFR(6)
    x0 += k1;  x1 += ks2 + 1u;
    TFR(17) TFR(29) TFR(16) TFR(24)
    x0 += ks2; x1 += k0 + 2u;
    TFR(13) TFR(15) TFR(26) TFR(6)
    x0 += k0;  x1 += k1 + 3u;
    TFR(17) TFR(29) TFR(16) TFR(24)
    x0 += k1;  x1 += ks2 + 4u;
    TFR(13) TFR(15) TFR(26) TFR(6)
    x0 += ks2; x1 += k0 + 5u;
#undef TFR
    return make_uint2(x0, x1);
}

// jax.random.normal, threefry-partitionable path (verified bit-matching, rel_err 3e-5).
__device__ __forceinline__ float jax_normal(uint2 key, uint32_t j) {
    uint2 r = tf2x32(key.x, key.y, 0u, j);
    uint32_t bits = r.x ^ r.y;
    float f = __uint_as_float((bits >> 9) | 0x3F800000u) - 1.0f;
    const float LO = -0.99999994f;               // nextafter(-1, 0)
    float u = fmaxf(LO, fmaf(f, 2.0f, LO));
    return 1.41421356f * erfinvf(u);
}

#define FMA2(d, a, b)      asm("fma.rn.f32x2 %0, %1, %2, %0;" : "+l"(d) : "l"(a), "l"(b))
#define PACK2(out, lo, hi) asm("mov.b64 %0, {%1, %2};" : "=l"(out) : "r"(lo), "r"(hi))
#define UNPACK2(lo, hi, in) asm("mov.b64 {%0, %1}, %2;" : "=r"(lo), "=r"(hi) : "l"(in))
#define DUP2(out, v)       PACK2(out, __float_as_uint(v), __float_as_uint(v))

// One full step for NP pairs starting at P0. Computes new latent into nl[].
template<int NP>
__device__ __forceinline__ void do_step(
    int P0, int q, int g0, int base, int st, float sigma, uint2 key,
    float wih0, float wih1, float bsum0, float bsum1,
    const float (*Lp)[HDIM][2], const float (*Xp)[TS][2], float4* nl)
{
    unsigned long long accA[NP], accB[NP];
    #pragma unroll
    for (int p = 0; p < NP; ++p) {
        float2 xv = *(const float2*)&Xp[P0 + p][st][0];
        PACK2(accA[p], __float_as_uint(fmaf(xv.x, wih0, bsum0)),
                       __float_as_uint(fmaf(xv.y, wih0, bsum0)));
        PACK2(accB[p], __float_as_uint(fmaf(xv.x, wih1, bsum1)),
                       __float_as_uint(fmaf(xv.y, wih1, bsum1)));
    }

    // matvec: acc{A,B}[p] += sum_h W[g{0,1}][h] * latent[pair][h], packed f32x2.
    // Depth-1 prefetch; 4 warps/SMSP hide the L1 latency.
    float4 wA = g_WpA[q], wB = g_WpB[q];
    #pragma unroll 1
    for (int h4 = 0; h4 < 64; ++h4) {
        int nxt = (((h4 + 1) & 63) << 7) + q;
        float4 nA = g_WpA[nxt], nB = g_WpB[nxt];
        unsigned long long ax, ay, az, aw, bx, by, bz, bw;
        DUP2(ax, wA.x); DUP2(ay, wA.y); DUP2(az, wA.z); DUP2(aw, wA.w);
        DUP2(bx, wB.x); DUP2(by, wB.y); DUP2(bz, wB.z); DUP2(bw, wB.w);
        #pragma unroll
        for (int p = 0; p < NP; ++p) {
            const ulonglong2* lptr = (const ulonglong2*)&Lp[P0 + p][h4 * 4][0]; // broadcast LDS
            ulonglong2 l01 = lptr[0];   // {b0,b1} pairs for h = 4h4, 4h4+1
            ulonglong2 l23 = lptr[1];   // h = 4h4+2, 4h4+3
            FMA2(accA[p], ax, l01.x);  FMA2(accB[p], bx, l01.x);
            FMA2(accA[p], ay, l01.y);  FMA2(accB[p], by, l01.y);
            FMA2(accA[p], az, l23.x);  FMA2(accB[p], bz, l23.x);
            FMA2(accA[p], aw, l23.y);  FMA2(accB[p], bw, l23.y);
        }
        wA = nA; wB = nB;
    }

    // tanh + noise + new latent (all Lp reads happen here, before the barrier)
    #pragma unroll
    for (int p = 0; p < NP; ++p) {
        int P = P0 + p;
        uint32_t alo, ahi, blo, bhi;
        UNPACK2(alo, ahi, accA[p]);
        UNPACK2(blo, bhi, accB[p]);
        float2 xv = *(const float2*)&Xp[P][st][0];
        float4 lv = *(const float4*)&Lp[P][g0][0];   // {b0g0, b1g0, b0g1, b1g1}
        uint32_t j00 = (uint32_t)(base + 2 * P) * HDIM + (uint32_t)g0;
        float n00 = jax_normal(key, j00);
        float n10 = jax_normal(key, j00 + HDIM);
        float n01 = jax_normal(key, j00 + 1);
        float n11 = jax_normal(key, j00 + HDIM + 1);
        // latent = ((latent + x) + h) + sigma * (0.1 * normal)  — reference order
        nl[p].x = ((lv.x + xv.x) + tanhf(__uint_as_float(alo))) + sigma * (0.1f * n00);
        nl[p].y = ((lv.y + xv.y) + tanhf(__uint_as_float(ahi))) + sigma * (0.1f * n10);
        nl[p].z = ((lv.z + xv.x) + tanhf(__uint_as_float(blo))) + sigma * (0.1f * n01);
        nl[p].w = ((lv.w + xv.y) + tanhf(__uint_as_float(bhi))) + sigma * (0.1f * n11);
    }
}

__global__ __launch_bounds__(256, 2)
void drnet_kernel(const float* __restrict__ img, const float* __restrict__ W_ih,
                  const float* __restrict__ b_ih, const float* __restrict__ b_hh,
                  float* __restrict__ out) {
    // Lp[pair][h][j] = latent[base + 2*pair + j][h]   (14 KB)
    __shared__ __align__(16) float Lp[7][HDIM][2];
    // Xp[pair][t][j] = x[base + 2*pair + j][t]        (14 KB)
    __shared__ __align__(16) float Xp[7][TS][2];
    __shared__ uint2 Ks[TS];                           // 2 KB

    const int t    = threadIdx.x;
    const int q    = t & 127;          // thread handles g0 = 2q, g1 = 2q+1
    const int half = t >> 7;           // half0 -> pairs 0..3, half1 -> pairs 4..6
    const int g0   = 2 * q;
    const int base = blockIdx.x * BC;

    Ks[t] = tf2x32(0u, 42u, 0u, (uint32_t)t);   // per-step split keys

    #pragma unroll
    for (int i = 0; i < BC; ++i) {
        int b = base + i; if (b >= BTOT) b = BTOT - 1;   // clamp (never stored)
        Xp[i >> 1][t][i & 1] = img[b * TS + t];           // coalesced over t
    }
    {   // zero latent
        float* lz = &Lp[0][0][0];
        for (int i = t; i < 7 * HDIM * 2; i += 256) lz[i] = 0.0f;
    }

    const float wih0  = W_ih[g0],            wih1  = W_ih[g0 + 1];
    const float bsum0 = b_ih[g0] + b_hh[g0], bsum1 = b_ih[g0 + 1] + b_hh[g0 + 1];
    __syncthreads();

    for (int st = 0; st < TS; ++st) {
        const float a     = (float)(257 - st) / 257.0f;   // a_t = (T - t + 1)/(T+1)
        const float sigma = sqrtf(a * (1.0f - a));
        const uint2 key   = Ks[st];

        float4 nl[4];
        if (half == 0)
            do_step<4>(0, q, g0, base, st, sigma, key, wih0, wih1, bsum0, bsum1,
                       Lp, Xp, nl);
        else
            do_step<3>(4, q, g0, base, st, sigma, key, wih0, wih1, bsum0, bsum1,
                       Lp, Xp, nl);

        __syncthreads();   // all matvec/latent reads complete before updates
        if (half == 0) {
            #pragma unroll
            for (int p = 0; p < 4; ++p) *(float4*)&Lp[p][g0][0] = nl[p];
        } else {
            #pragma unroll
            for (int p = 0; p < 3; ++p) *(float4*)&Lp[4 + p][g0][0] = nl[p];
        }
        __syncthreads();   // updates visible before next step's matvec
    }

    const int pA = half ? 4 : 0, pB = half ? 7 : 4;
    for (int P = pA; P < pB; ++P) {
        int b0 = base + 2 * P;
        float4 lv = *(const float4*)&Lp[P][g0][0];
        if (b0 < BTOT)     { out[b0 * HDIM + g0] = lv.x;  out[b0 * HDIM + g0 + 1] = lv.z; }
        if (b0 + 1 < BTOT) { out[(b0 + 1) * HDIM + g0] = lv.y;
                             out[(b0 + 1) * HDIM + g0 + 1] = lv.w; }
    }
}

extern "C" void kernel_launch(void* const* d_in, const int* in_sizes, int n_in,
                              void* d_out, int out_size) {
    // metadata order: T (int scalar), flat_img, W_ih, W_hh, b_ih, b_hh.
    int o = (n_in >= 6) ? (n_in - 5) : 0;
    const float* img  = (const float*)d_in[o + 0];
    const float* W_ih = (const float*)d_in[o + 1];
    const float* W_hh = (const float*)d_in[o + 2];
    const float* b_ih = (const float*)d_in[o + 3];
    const float* b_hh = (const float*)d_in[o + 4];

    pack_w_kernel<<<64, 256>>>(W_hh);
    drnet_kernel<<<NBLK, 256>>>(img, W_ih, b_ih, b_hh, (float*)d_out);
}